// round 1
// baseline (speedup 1.0000x reference)
#include <cuda_runtime.h>

// LIF scan: x [B, T, N] -> spikes [B, T, N]
//   mem = TAU*mem + x;  spike = (mem > V_TH);  mem *= (1 - spike)
// Parallel over (B, N); sequential over T in registers.

#define B_DIM 64
#define T_DIM 128
#define N_DIM 8192

__global__ void __launch_bounds__(256) lif_kernel(const float4* __restrict__ x,
                                                  float4* __restrict__ out) {
    const float V_TH = 1.0f;
    const float TAU  = 0.25f;

    const int n4_per_b = N_DIM / 4;            // 2048 float4 per time-row
    int tid = blockIdx.x * blockDim.x + threadIdx.x;   // 0 .. B*N/4-1
    int b   = tid / n4_per_b;
    int n4  = tid - b * n4_per_b;

    // base index (in float4 units) of x[b, 0, n4*4]
    long base = (long)b * T_DIM * n4_per_b + n4;

    float4 mem = make_float4(0.f, 0.f, 0.f, 0.f);

#pragma unroll 4
    for (int t = 0; t < T_DIM; ++t) {
        long idx = base + (long)t * n4_per_b;
        float4 v = x[idx];

        mem.x = TAU * mem.x + v.x;
        mem.y = TAU * mem.y + v.y;
        mem.z = TAU * mem.z + v.z;
        mem.w = TAU * mem.w + v.w;

        float4 s;
        s.x = (mem.x > V_TH) ? 1.0f : 0.0f;
        s.y = (mem.y > V_TH) ? 1.0f : 0.0f;
        s.z = (mem.z > V_TH) ? 1.0f : 0.0f;
        s.w = (mem.w > V_TH) ? 1.0f : 0.0f;

        // reset-to-zero on spike
        mem.x = (s.x > 0.0f) ? 0.0f : mem.x;
        mem.y = (s.y > 0.0f) ? 0.0f : mem.y;
        mem.z = (s.z > 0.0f) ? 0.0f : mem.z;
        mem.w = (s.w > 0.0f) ? 0.0f : mem.w;

        out[idx] = s;
    }
}

extern "C" void kernel_launch(void* const* d_in, const int* in_sizes, int n_in,
                              void* d_out, int out_size) {
    const float4* x = (const float4*)d_in[0];
    float4* out     = (float4*)d_out;

    int total_threads = B_DIM * (N_DIM / 4);   // 131072
    int block = 256;
    int grid  = total_threads / block;         // 512
    lif_kernel<<<grid, block>>>(x, out);
}